// round 6
// baseline (speedup 1.0000x reference)
#include <cuda_runtime.h>
#include <cuda_bf16.h>
#include <cstdint>

// ---------------- problem constants ----------------
#define Bv 8
#define Qv 1024
#define Sv 2048
#define Dm 1024
#define Hv 16
#define DH 64
#define MT 128            // q rows per CTA
#define ST 64             // s per tile
#define NTILES (Sv / ST)  // 32
#define NTH 256

// bf16 tile pitch (elements / bytes)
#define PB  72
#define PBB (PB * 2)      // 144 B per row

// ---------------- smem layout (bytes) ----------------
#define SM_QHI   0
#define SM_QLO   (SM_QHI + MT * PBB)      // 18432
#define SM_KHI   (SM_QLO + MT * PBB)      // 36864
#define SM_KLO   (SM_KHI + ST * PBB)      // 46080
#define SM_VHI   (SM_KLO + ST * PBB)      // 55296
#define SM_VLO   (SM_VHI + ST * PBB)      // 64512
#define SM_MASK  (SM_VLO + ST * PBB)      // 73728  (2048 u8)
#define SM_STAGE (SM_MASK + 2048)         // 75776
#define STP 68                            // stage pitch (floats)
#define SMEM_TOTAL (SM_STAGE + MT * STP * 4)   // 110592

// ---------------- helpers ----------------
__device__ __forceinline__ uint32_t su32(const void* p) {
    uint32_t a;
    asm("{ .reg .u64 t; cvta.to.shared.u64 t, %1; cvt.u32.u64 %0, t; }" : "=r"(a) : "l"(p));
    return a;
}

__device__ __forceinline__ void ldm4(uint32_t* r, uint32_t a) {
    asm volatile("ldmatrix.sync.aligned.m8n8.x4.shared.b16 {%0,%1,%2,%3}, [%4];"
        : "=r"(r[0]), "=r"(r[1]), "=r"(r[2]), "=r"(r[3]) : "r"(a));
}
__device__ __forceinline__ void ldm4t(uint32_t* r, uint32_t a) {
    asm volatile("ldmatrix.sync.aligned.m8n8.x4.trans.shared.b16 {%0,%1,%2,%3}, [%4];"
        : "=r"(r[0]), "=r"(r[1]), "=r"(r[2]), "=r"(r[3]) : "r"(a));
}
__device__ __forceinline__ void mma16816(float* d, const uint32_t* a, uint32_t b0, uint32_t b1) {
    asm volatile("mma.sync.aligned.m16n8k16.row.col.f32.bf16.bf16.f32 "
        "{%0,%1,%2,%3}, {%4,%5,%6,%7}, {%8,%9}, {%0,%1,%2,%3};"
        : "+f"(d[0]), "+f"(d[1]), "+f"(d[2]), "+f"(d[3])
        : "r"(a[0]), "r"(a[1]), "r"(a[2]), "r"(a[3]), "r"(b0), "r"(b1));
}

// pack two fp32 into bf16x2 hi + bf16x2 lo (split)
__device__ __forceinline__ void pack2(float e0, float e1, uint32_t& hi, uint32_t& lo) {
    __nv_bfloat162 h = __floats2bfloat162_rn(e0, e1);
    hi = *(uint32_t*)&h;
    float f0 = __bfloat162float(__low2bfloat16(h));
    float f1 = __bfloat162float(__high2bfloat16(h));
    __nv_bfloat162 l = __floats2bfloat162_rn(e0 - f0, e1 - f1);
    lo = *(uint32_t*)&l;
}

// split a float2 into hi/lo bf16x2 tiles at (row, dpair)
__device__ __forceinline__ void split_store(char* hib, char* lob, int row, int dp, float2 v) {
    uint32_t h, l;
    pack2(v.x, v.y, h, l);
    *(uint32_t*)(hib + row * PBB + dp * 4) = h;
    *(uint32_t*)(lob + row * PBB + dp * 4) = l;
}

// ======================= K1: fused attention (single kernel) =======================
extern __shared__ char smem[];

__global__ void __launch_bounds__(NTH, 2)
attn_k1(const float* __restrict__ Qg, const float* __restrict__ Kg,
        const float* __restrict__ Vg, const int* __restrict__ Mg,
        float* __restrict__ outg, float* __restrict__ attng)
{
    const int tid  = threadIdx.x;
    const int lane = tid & 31;
    const int wq   = tid >> 5;          // warp -> q rows [wq*16, wq*16+16)
    const int q0   = blockIdx.x * MT;
    const int h    = blockIdx.y;
    const int b    = blockIdx.z;

    const uint32_t sb = su32(smem);
    unsigned char* mk = (unsigned char*)(smem + SM_MASK);
    float* stg = (float*)(smem + SM_STAGE);

    // Q scale folds 1/sqrt(Dh)=0.125 and log2(e): exp(s) == exp2(s_scaled)
    const float QSCALE = 0.125f * 1.44269504088896f;

    // ---- prologue: Q (scaled, hi/lo split) + mask + K_0 smem + V_0 regs ----
    #pragma unroll 4
    for (int it = 0; it < 16; it++) {
        int idx = tid + it * NTH;
        int m = idx >> 5, dp = idx & 31;
        float2 v = *(const float2*)(Qg + ((size_t)(b * Qv + q0 + m)) * Dm + h * DH + dp * 2);
        v.x *= QSCALE; v.y *= QSCALE;
        split_store(smem + SM_QHI, smem + SM_QLO, m, dp, v);
    }
    for (int s = tid; s < Sv; s += NTH)
        mk[s] = (unsigned char)Mg[(size_t)b * Sv + s];

    const float* Kp = Kg + (size_t)b * Sv * Dm + h * DH;
    const float* Vp = Vg + (size_t)b * Sv * Dm + h * DH;

    const int prr = tid >> 5;        // prefetch row (per-it base), dp below
    const int pdp = tid & 31;

    float2 kk[8], vv[8];
    #pragma unroll
    for (int it = 0; it < 8; it++) {
        int rr = prr + it * 8;
        split_store(smem + SM_KHI, smem + SM_KLO, rr, pdp,
                    *(const float2*)(Kp + (size_t)rr * Dm + pdp * 2));
        vv[it] = *(const float2*)(Vp + (size_t)rr * Dm + pdp * 2);
    }
    __syncthreads();

    // ---- per-thread ldmatrix addresses ----
    const uint32_t aAoff = (uint32_t)((wq * 16 + (lane & 15)) * PBB + ((lane & 16) >> 4) * 16);
    const uint32_t aAhi = sb + SM_QHI + aAoff;
    const uint32_t aAlo = sb + SM_QLO + aAoff;
    const uint32_t aBoff = (uint32_t)(((lane & 7) + ((lane & 16) >> 1)) * PBB + ((lane & 8) << 1));
    const uint32_t aVoff = (uint32_t)(((lane & 7) + (lane & 8)) * PBB + ((lane >> 4) & 1) * 16);

    const int r = lane >> 2, c = lane & 3;

    float O[8][4];
    #pragma unroll
    for (int nt = 0; nt < 8; nt++)
        #pragma unroll
        for (int j = 0; j < 4; j++) O[nt][j] = 0.0f;
    float rsl = 0.0f, rsh = 0.0f;

    for (int i = 0; i < NTILES; i++) {
        // A: commit V_i regs -> smem
        #pragma unroll
        for (int it = 0; it < 8; it++)
            split_store(smem + SM_VHI, smem + SM_VLO, prr + it * 8, pdp, vv[it]);

        // B: prefetch K_{i+1}, V_{i+1} into regs (latency hidden behind this tile)
        if (i + 1 < NTILES) {
            #pragma unroll
            for (int it = 0; it < 8; it++) {
                int rr = prr + it * 8;
                kk[it] = *(const float2*)(Kp + (size_t)((i + 1) * ST + rr) * Dm + pdp * 2);
                vv[it] = *(const float2*)(Vp + (size_t)((i + 1) * ST + rr) * Dm + pdp * 2);
            }
        }

        // C: MMA1: S = Qs @ K^T (hi*hi + hi*lo + lo*hi)
        float S[8][4];
        #pragma unroll
        for (int nt = 0; nt < 8; nt++)
            #pragma unroll
            for (int j = 0; j < 4; j++) S[nt][j] = 0.0f;

        #pragma unroll
        for (int k4 = 0; k4 < 4; k4++) {
            uint32_t ah[4], al[4];
            ldm4(ah, aAhi + k4 * 32);
            ldm4(al, aAlo + k4 * 32);
            #pragma unroll
            for (int np = 0; np < 4; np++) {
                uint32_t bo = aBoff + np * 16 * PBB + k4 * 32;
                uint32_t bh[4], bl[4];
                ldm4(bh, sb + SM_KHI + bo);
                ldm4(bl, sb + SM_KLO + bo);
                mma16816(S[2*np],   ah, bh[0], bh[1]);
                mma16816(S[2*np+1], ah, bh[2], bh[3]);
                mma16816(S[2*np],   ah, bl[0], bl[1]);
                mma16816(S[2*np+1], ah, bl[2], bl[3]);
                mma16816(S[2*np],   al, bh[0], bh[1]);
                mma16816(S[2*np+1], al, bh[2], bh[3]);
            }
        }

        // D: Ksmem free for refill; Vsmem visible for MMA2
        __syncthreads();

        // E: mask * exp2, rowsum, stage (unnormalized)
        const int s0 = i * ST;
        #pragma unroll
        for (int nt = 0; nt < 8; nt++) {
            int col = nt * 8 + 2 * c;
            float m0 = (float)mk[s0 + col], m1 = (float)mk[s0 + col + 1];
            float e0 = m0 * exp2f(S[nt][0]);
            float e1 = m1 * exp2f(S[nt][1]);
            float e2 = m0 * exp2f(S[nt][2]);
            float e3 = m1 * exp2f(S[nt][3]);
            rsl += e0 + e1; rsh += e2 + e3;
            S[nt][0] = e0; S[nt][1] = e1; S[nt][2] = e2; S[nt][3] = e3;
            *(float2*)&stg[(wq * 16 + r)     * STP + col] = make_float2(e0, e1);
            *(float2*)&stg[(wq * 16 + r + 8) * STP + col] = make_float2(e2, e3);
        }

        // F: coalesced attention write (unnormalized e); STG drains during MMA2
        __syncwarp();
        #pragma unroll
        for (int it = 0; it < 8; it++) {
            int row2 = it * 2 + (lane >> 4);
            int c4   = lane & 15;
            float4 v = *(float4*)&stg[(wq * 16 + row2) * STP + c4 * 4];
            *(float4*)(attng + (((size_t)(b * Qv + q0 + wq * 16 + row2)) * Hv + h) * Sv
                       + s0 + c4 * 4) = v;
        }

        // G: MMA2: O += P @ V (Phi*Vhi + Phi*Vlo + Plo*Vhi), P from registers
        #pragma unroll
        for (int kt = 0; kt < 4; kt++) {
            uint32_t ph[4], pl[4];
            pack2(S[2*kt][0],   S[2*kt][1],   ph[0], pl[0]);
            pack2(S[2*kt][2],   S[2*kt][3],   ph[1], pl[1]);
            pack2(S[2*kt+1][0], S[2*kt+1][1], ph[2], pl[2]);
            pack2(S[2*kt+1][2], S[2*kt+1][3], ph[3], pl[3]);
            #pragma unroll
            for (int np = 0; np < 4; np++) {
                uint32_t bo = aVoff + kt * 16 * PBB + np * 32;
                uint32_t vh4[4], vl4[4];
                ldm4t(vh4, sb + SM_VHI + bo);
                ldm4t(vl4, sb + SM_VLO + bo);
                mma16816(O[2*np],   ph, vh4[0], vh4[1]);
                mma16816(O[2*np+1], ph, vh4[2], vh4[3]);
                mma16816(O[2*np],   ph, vl4[0], vl4[1]);
                mma16816(O[2*np+1], ph, vl4[2], vl4[3]);
                mma16816(O[2*np],   pl, vh4[0], vh4[1]);
                mma16816(O[2*np+1], pl, vh4[2], vh4[3]);
            }
        }

        // H: commit K_{i+1} regs -> smem
        if (i + 1 < NTILES) {
            #pragma unroll
            for (int it = 0; it < 8; it++)
                split_store(smem + SM_KHI, smem + SM_KLO, prr + it * 8, pdp, kk[it]);
        }

        // J: Ksmem_{i+1} visible; Vsmem free (all warps past MMA2)
        __syncthreads();
    }

    // ---- rowsum reduce, rinv, normalize O, write out ----
    rsl += __shfl_xor_sync(0xffffffffu, rsl, 1);
    rsl += __shfl_xor_sync(0xffffffffu, rsl, 2);
    rsh += __shfl_xor_sync(0xffffffffu, rsh, 1);
    rsh += __shfl_xor_sync(0xffffffffu, rsh, 2);
    const float il = 1.0f / (rsl + 1e-13f);
    const float ih = 1.0f / (rsh + 1e-13f);

    // publish rinv per q-row into (dead) stage area
    if (c == 0) {
        stg[wq * 16 + r]     = il;
        stg[wq * 16 + r + 8] = ih;
    }

    float* orow0 = outg + (size_t)(b * Qv + q0 + wq * 16 + r)     * Dm + h * DH;
    float* orow1 = outg + (size_t)(b * Qv + q0 + wq * 16 + r + 8) * Dm + h * DH;
    #pragma unroll
    for (int nt = 0; nt < 8; nt++) {
        int col = nt * 8 + 2 * c;
        *(float2*)(orow0 + col) = make_float2(O[nt][0] * il, O[nt][1] * il);
        *(float2*)(orow1 + col) = make_float2(O[nt][2] * ih, O[nt][3] * ih);
    }

    __syncthreads();   // rinv table visible

    // ---- fused rescale tail: normalize this CTA's attn block in place ----
    // 128 rows x 2048 cols = 65536 float4, 256 per thread, coalesced.
    #pragma unroll 4
    for (int it = 0; it < (MT * (Sv / 4)) / NTH; it++) {
        int idx = tid + it * NTH;
        int row = idx >> 9;
        int col = idx & 511;
        float ri = stg[row];
        float4* p = (float4*)(attng + (((size_t)(b * Qv + q0 + row)) * Hv + h) * Sv) + col;
        float4 v = *p;
        v.x *= ri; v.y *= ri; v.z *= ri; v.w *= ri;
        *p = v;
    }
}

// ======================= launch =======================
extern "C" void kernel_launch(void* const* d_in, const int* in_sizes, int n_in,
                              void* d_out, int out_size)
{
    const float* Qg = (const float*)d_in[0];
    const float* Kg = (const float*)d_in[1];
    const float* Vg = (const float*)d_in[2];
    const int*   Mg = (const int*)d_in[3];

    float* outg  = (float*)d_out;                     // [B,Q,D]
    float* attng = outg + (size_t)Bv * Qv * Dm;       // [B,Q,H,S]

    cudaFuncSetAttribute(attn_k1, cudaFuncAttributeMaxDynamicSharedMemorySize, SMEM_TOTAL);

    dim3 grid(Qv / MT, Hv, Bv);                       // (8,16,8) = 1024 CTAs
    attn_k1<<<grid, NTH, SMEM_TOTAL>>>(Qg, Kg, Vg, Mg, outg, attng);
}